// round 2
// baseline (speedup 1.0000x reference)
#include <cuda_runtime.h>

#define N_NODES 6144
#define NFEAT   512
#define NHID    256
#define NHEADS  4
#define DHEAD   64
#define NEMBED  128
#define LRELU_ALPHA 0.2f
#define MAXDEG  256

typedef unsigned long long u64;

// Scratch (device globals; no runtime allocation allowed)
__device__ float g_whcat[N_NODES * NHID];   // Wh in [node][head*64+d] layout
__device__ float g_s[NHEADS * N_NODES];
__device__ float g_t[NHEADS * N_NODES];
__device__ float g_hcat[N_NODES * NHID];    // post-attention, post-ELU hidden
__device__ int   g_nbr[N_NODES * MAXDEG];   // compacted neighbor lists
__device__ int   g_deg[N_NODES];

// ---- f32x2 packed helpers -------------------------------------------------
__device__ __forceinline__ u64 pk2(float lo, float hi) {
    u64 r; asm("mov.b64 %0, {%1, %2};" : "=l"(r) : "f"(lo), "f"(hi)); return r;
}
__device__ __forceinline__ void upk2(u64 v, float& lo, float& hi) {
    asm("mov.b64 {%0, %1}, %2;" : "=f"(lo), "=f"(hi) : "l"(v));
}
__device__ __forceinline__ void ffma2(u64& d, u64 a, u64 b) {
    asm("fma.rn.f32x2 %0, %1, %2, %0;" : "+l"(d) : "l"(a), "l"(b));
}

// ---------------------------------------------------------------------------
// K0: adjacency row compaction -> neighbor lists (runs on side stream,
//     overlapped with K1). One block per node.
// ---------------------------------------------------------------------------
__global__ __launch_bounds__(256) void k0_compact(
    const int* __restrict__ adj, int* __restrict__ nbr, int* __restrict__ deg)
{
    __shared__ int scount;
    const int i   = blockIdx.x;
    const int tid = threadIdx.x;
    if (tid == 0) scount = 0;
    __syncthreads();

    int* row = nbr + (size_t)i * MAXDEG;
    const int4* arow = (const int4*)(adj + (size_t)i * N_NODES);
    for (int q = tid; q < N_NODES / 4; q += 256) {
        int4 v = arow[q];
        if (v.x) { int p = atomicAdd(&scount, 1); if (p < MAXDEG) row[p] = q * 4 + 0; }
        if (v.y) { int p = atomicAdd(&scount, 1); if (p < MAXDEG) row[p] = q * 4 + 1; }
        if (v.z) { int p = atomicAdd(&scount, 1); if (p < MAXDEG) row[p] = q * 4 + 2; }
        if (v.w) { int p = atomicAdd(&scount, 1); if (p < MAXDEG) row[p] = q * 4 + 3; }
    }
    __syncthreads();
    if (tid == 0) deg[i] = min(scount, MAXDEG);
}

// ---------------------------------------------------------------------------
// K1: Wh_cat = x @ W2   [6144,512]@[512,256] -> [6144,256]
//     128x128 tile, BK=8, 256 threads, 8x8 microtile with packed f32x2 FMA.
//     Accumulators packed in pairs over the row (i) dimension.
// ---------------------------------------------------------------------------
__global__ __launch_bounds__(256) void k1_gemm(
    const float* __restrict__ x, const float* __restrict__ W,
    float* __restrict__ C)
{
    __shared__ float As[8][128];
    __shared__ float Bs[8][128];

    const int m0 = blockIdx.x * 128;
    const int c0 = blockIdx.y * 128;
    const int t  = threadIdx.x;
    const int tx = t & 15;   // col group (8 cols)
    const int ty = t >> 4;   // row group (8 rows)

    u64 acc2[4][8];          // rows (2ip, 2ip+1) x 8 cols
#pragma unroll
    for (int ip = 0; ip < 4; ip++)
#pragma unroll
        for (int j = 0; j < 8; j++) acc2[ip][j] = 0ull;

    const int a_row = t >> 1;
    const int a_kq  = t & 1;
    const int b_k  = t >> 5;
    const int b_cq = (t & 31) << 2;
    const int b_c  = c0 + b_cq;
    const int b_head = b_c >> 6;
    const int b_d    = b_c & 63;

    for (int kk = 0; kk < NFEAT; kk += 8) {
        float4 av = *(const float4*)(x + (size_t)(m0 + a_row) * NFEAT + kk + a_kq * 4);
        As[a_kq * 4 + 0][a_row] = av.x;
        As[a_kq * 4 + 1][a_row] = av.y;
        As[a_kq * 4 + 2][a_row] = av.z;
        As[a_kq * 4 + 3][a_row] = av.w;
        float4 bv = *(const float4*)(W + (size_t)b_head * NFEAT * DHEAD
                                       + (size_t)(kk + b_k) * DHEAD + b_d);
        *(float4*)&Bs[b_k][b_cq] = bv;
        __syncthreads();

#pragma unroll
        for (int k = 0; k < 8; k++) {
            // a pairs: rows (ty*8+2ip, ty*8+2ip+1) packed straight from smem
            ulonglong2 aa0 = *(const ulonglong2*)&As[k][ty * 8 + 0];
            ulonglong2 aa1 = *(const ulonglong2*)&As[k][ty * 8 + 4];
            u64 a2[4] = {aa0.x, aa0.y, aa1.x, aa1.y};
            float b[8];
            *(float4*)(b + 0) = *(const float4*)&Bs[k][tx * 8 + 0];
            *(float4*)(b + 4) = *(const float4*)&Bs[k][tx * 8 + 4];
            u64 b2[8];
#pragma unroll
            for (int j = 0; j < 8; j++) b2[j] = pk2(b[j], b[j]);
#pragma unroll
            for (int ip = 0; ip < 4; ip++)
#pragma unroll
                for (int j = 0; j < 8; j++)
                    ffma2(acc2[ip][j], a2[ip], b2[j]);
        }
        __syncthreads();
    }

#pragma unroll
    for (int ip = 0; ip < 4; ip++) {
        float lo[8], hi[8];
#pragma unroll
        for (int j = 0; j < 8; j++) upk2(acc2[ip][j], lo[j], hi[j]);
        float* d0 = C + (size_t)(m0 + ty * 8 + 2 * ip + 0) * NHID + c0 + tx * 8;
        float* d1 = C + (size_t)(m0 + ty * 8 + 2 * ip + 1) * NHID + c0 + tx * 8;
        *(float4*)(d0 + 0) = make_float4(lo[0], lo[1], lo[2], lo[3]);
        *(float4*)(d0 + 4) = make_float4(lo[4], lo[5], lo[6], lo[7]);
        *(float4*)(d1 + 0) = make_float4(hi[0], hi[1], hi[2], hi[3]);
        *(float4*)(d1 + 4) = make_float4(hi[4], hi[5], hi[6], hi[7]);
    }
}

// ---------------------------------------------------------------------------
// K2: s[h][i] = Wh[i][h*64:] . a_src[h],  t likewise
// ---------------------------------------------------------------------------
__global__ __launch_bounds__(256) void k2_st(
    const float* __restrict__ wh, const float* __restrict__ a_src,
    const float* __restrict__ a_dst,
    float* __restrict__ s, float* __restrict__ t)
{
    int id = blockIdx.x * blockDim.x + threadIdx.x;
    if (id >= NHEADS * N_NODES) return;
    int h = id / N_NODES;
    int i = id - h * N_NODES;
    const float* row = wh + (size_t)i * NHID + h * DHEAD;
    const float* as  = a_src + h * DHEAD;
    const float* ad  = a_dst + h * DHEAD;
    float ss = 0.f, tt = 0.f;
#pragma unroll 8
    for (int d = 0; d < DHEAD; d++) {
        float v = row[d];
        ss += v * as[d];
        tt += v * ad[d];
    }
    s[id] = ss;
    t[id] = tt;
}

// ---------------------------------------------------------------------------
// K3: per-node sparse masked softmax + aggregation + per-head ELU.
//     Neighbor lists precomputed by K0. One block (256 thr) per node.
// ---------------------------------------------------------------------------
__global__ __launch_bounds__(256) void k3_attn(
    const int* __restrict__ nbr, const int* __restrict__ degv,
    const float* __restrict__ wh,
    const float* __restrict__ s, const float* __restrict__ t,
    float* __restrict__ hcat)
{
    __shared__ int   sidx[MAXDEG];
    __shared__ float sw[NHEADS * MAXDEG];
    __shared__ float srs[NHEADS];

    const int i   = blockIdx.x;
    const int tid = threadIdx.x;
    const int deg = degv[i];

    for (int j = tid; j < deg; j += 256) sidx[j] = nbr[(size_t)i * MAXDEG + j];
    __syncthreads();

    // e[h][j] = lrelu(s[h][i] + t[h][j])
    for (int m = tid; m < deg * NHEADS; m += 256) {
        int j = m >> 2;
        int h = m & 3;
        int jj = sidx[j];
        float e = s[h * N_NODES + i] + t[h * N_NODES + jj];
        e = e > 0.f ? e : LRELU_ALPHA * e;
        sw[h * MAXDEG + j] = e;
    }
    __syncthreads();

    // per-head softmax (warp h -> head h)
    const int warp = tid >> 5;
    const int lane = tid & 31;
    if (warp < NHEADS) {
        const int h = warp;
        float mx = -3.4e38f;
        for (int j = lane; j < deg; j += 32) mx = fmaxf(mx, sw[h * MAXDEG + j]);
#pragma unroll
        for (int o = 16; o; o >>= 1) mx = fmaxf(mx, __shfl_xor_sync(0xffffffffu, mx, o));
        float sum = 0.f;
        for (int j = lane; j < deg; j += 32) {
            float w = __expf(sw[h * MAXDEG + j] - mx);
            sw[h * MAXDEG + j] = w;
            sum += w;
        }
#pragma unroll
        for (int o = 16; o; o >>= 1) sum += __shfl_xor_sync(0xffffffffu, sum, o);
        if (lane == 0) srs[h] = (sum > 0.f) ? 1.f / sum : 0.f;
    }
    __syncthreads();

    // aggregate + per-head ELU; thread = (head tid>>6, dim tid&63)
    const int h = tid >> 6;
    float acc = 0.f;
    const float* whb = wh + tid;   // tid == h*64 + d == column in concat layout
#pragma unroll 4
    for (int j = 0; j < deg; j++) {
        int jj = sidx[j];
        acc += sw[h * MAXDEG + j] * whb[(size_t)jj * NHID];
    }
    acc *= srs[h];
    acc = acc > 0.f ? acc : (__expf(acc) - 1.f);
    hcat[(size_t)i * NHID + tid] = acc;
}

// ---------------------------------------------------------------------------
// K4: out = elu(hcat @ lin_w^T + b)   [6144,256]@[256,128] -> [6144,128]
//     32x128 tile (full N), BK=16, 128 threads, 4x8 microtile, f32x2 FMA.
//     grid = 192 blocks.
// ---------------------------------------------------------------------------
__global__ __launch_bounds__(128) void k4_out(
    const float* __restrict__ hcat, const float* __restrict__ lin_w,
    const float* __restrict__ lin_b, float* __restrict__ out)
{
    __shared__ float As[16][32];
    __shared__ float Bs[16][128];

    const int m0 = blockIdx.x * 32;
    const int t  = threadIdx.x;
    const int tx = t & 15;   // col group (8 cols)
    const int ty = t >> 4;   // row group (4 rows)

    u64 acc2[2][8];
#pragma unroll
    for (int ip = 0; ip < 2; ip++)
#pragma unroll
        for (int j = 0; j < 8; j++) acc2[ip][j] = 0ull;

    // A load: 32 rows x 16 k = 128 float4; thread: row = t&31, kq = t>>5
    const int a_row = t & 31;
    const int a_kq  = t >> 5;
    // B load: 128 n x 16 k = 512 float4; 4 per thread: n = 32*it + (t>>2), kq = t&3
    const int b_nb = t >> 2;
    const int b_kq = t & 3;

    for (int kk = 0; kk < NHID; kk += 16) {
        float4 av = *(const float4*)(hcat + (size_t)(m0 + a_row) * NHID + kk + a_kq * 4);
        As[a_kq * 4 + 0][a_row] = av.x;
        As[a_kq * 4 + 1][a_row] = av.y;
        As[a_kq * 4 + 2][a_row] = av.z;
        As[a_kq * 4 + 3][a_row] = av.w;
#pragma unroll
        for (int it = 0; it < 4; it++) {
            int n = it * 32 + b_nb;
            float4 bv = *(const float4*)(lin_w + (size_t)n * NHID + kk + b_kq * 4);
            Bs[b_kq * 4 + 0][n] = bv.x;
            Bs[b_kq * 4 + 1][n] = bv.y;
            Bs[b_kq * 4 + 2][n] = bv.z;
            Bs[b_kq * 4 + 3][n] = bv.w;
        }
        __syncthreads();

#pragma unroll
        for (int k = 0; k < 16; k++) {
            ulonglong2 aa = *(const ulonglong2*)&As[k][ty * 4];
            u64 a2[2] = {aa.x, aa.y};
            float b[8];
            *(float4*)(b + 0) = *(const float4*)&Bs[k][tx * 8 + 0];
            *(float4*)(b + 4) = *(const float4*)&Bs[k][tx * 8 + 4];
            u64 b2[8];
#pragma unroll
            for (int j = 0; j < 8; j++) b2[j] = pk2(b[j], b[j]);
#pragma unroll
            for (int ip = 0; ip < 2; ip++)
#pragma unroll
                for (int j = 0; j < 8; j++)
                    ffma2(acc2[ip][j], a2[ip], b2[j]);
        }
        __syncthreads();
    }

#pragma unroll
    for (int ip = 0; ip < 2; ip++) {
        float lo[8], hi[8];
#pragma unroll
        for (int j = 0; j < 8; j++) {
            upk2(acc2[ip][j], lo[j], hi[j]);
            float bb = lin_b[tx * 8 + j];
            lo[j] += bb;  hi[j] += bb;
            lo[j] = lo[j] > 0.f ? lo[j] : (__expf(lo[j]) - 1.f);
            hi[j] = hi[j] > 0.f ? hi[j] : (__expf(hi[j]) - 1.f);
        }
        float* d0 = out + (size_t)(m0 + ty * 4 + 2 * ip + 0) * NEMBED + tx * 8;
        float* d1 = out + (size_t)(m0 + ty * 4 + 2 * ip + 1) * NEMBED + tx * 8;
        *(float4*)(d0 + 0) = make_float4(lo[0], lo[1], lo[2], lo[3]);
        *(float4*)(d0 + 4) = make_float4(lo[4], lo[5], lo[6], lo[7]);
        *(float4*)(d1 + 0) = make_float4(hi[0], hi[1], hi[2], hi[3]);
        *(float4*)(d1 + 4) = make_float4(hi[4], hi[5], hi[6], hi[7]);
    }
}

// ---------------------------------------------------------------------------
static cudaStream_t g_side = nullptr;
static cudaEvent_t  g_ev_fork = nullptr;
static cudaEvent_t  g_ev_join = nullptr;

extern "C" void kernel_launch(void* const* d_in, const int* in_sizes, int n_in,
                              void* d_out, int out_size)
{
    const float* x     = (const float*)d_in[0];
    const int*   adj   = (const int*)  d_in[1];
    const float* W     = (const float*)d_in[2];
    const float* a_src = (const float*)d_in[3];
    const float* a_dst = (const float*)d_in[4];
    const float* lin_w = (const float*)d_in[5];
    const float* lin_b = (const float*)d_in[6];
    float* out = (float*)d_out;

    // One-time host-side stream/event setup (no device memory involved).
    // First call is the pre-capture correctness run, so creation happens
    // outside capture; the captured call reuses them (fork-join pattern).
    if (!g_side) {
        cudaStreamCreateWithFlags(&g_side, cudaStreamNonBlocking);
        cudaEventCreateWithFlags(&g_ev_fork, cudaEventDisableTiming);
        cudaEventCreateWithFlags(&g_ev_join, cudaEventDisableTiming);
    }

    float* whcat; cudaGetSymbolAddress((void**)&whcat, g_whcat);
    float* s;     cudaGetSymbolAddress((void**)&s, g_s);
    float* t;     cudaGetSymbolAddress((void**)&t, g_t);
    float* hcat;  cudaGetSymbolAddress((void**)&hcat, g_hcat);
    int*   nbr;   cudaGetSymbolAddress((void**)&nbr, g_nbr);
    int*   deg;   cudaGetSymbolAddress((void**)&deg, g_deg);

    // Fork: adjacency compaction runs concurrently with K1/K2.
    cudaEventRecord(g_ev_fork, 0);
    cudaStreamWaitEvent(g_side, g_ev_fork, 0);
    k0_compact<<<N_NODES, 256, 0, g_side>>>(adj, nbr, deg);
    cudaEventRecord(g_ev_join, g_side);

    dim3 g1(N_NODES / 128, NHID / 128);
    k1_gemm<<<g1, 256>>>(x, W, whcat);
    k2_st<<<(NHEADS * N_NODES + 255) / 256, 256>>>(whcat, a_src, a_dst, s, t);

    // Join: K3 needs both the neighbor lists and Wh/s/t.
    cudaStreamWaitEvent(0, g_ev_join, 0);
    k3_attn<<<N_NODES, 256>>>(nbr, deg, whcat, s, t, hcat);

    k4_out<<<N_NODES / 32, 128>>>(hcat, lin_w, lin_b, out);
}

// round 4
// speedup vs baseline: 1.2762x; 1.2762x over previous
#include <cuda_runtime.h>
#include <cuda_bf16.h>

#define N_NODES 6144
#define NFEAT   512
#define NHID    256
#define NHEADS  4
#define DHEAD   64
#define NEMBED  128
#define LRELU_ALPHA 0.2f
#define MAXDEG  256
#define KCAT    1536           // 3 * NFEAT (split-bf16 concat)

typedef unsigned int u32;

// Scratch (device globals; no runtime allocation allowed)
__device__ float g_whcat[N_NODES * NHID];
__device__ float g_s[NHEADS * N_NODES];
__device__ float g_t[NHEADS * N_NODES];
__device__ float g_hcat[N_NODES * NHID];
__device__ __nv_bfloat16 g_abf[N_NODES * KCAT];   // [x_hi | x_hi | x_lo]
__device__ __nv_bfloat16 g_bbf[NHID * KCAT];      // [w_hi | w_lo | w_hi], [N][K]

// ---------------------------------------------------------------------------
// P1: build A' bf16  [x_hi | x_hi | x_lo]
// ---------------------------------------------------------------------------
__global__ __launch_bounds__(256) void p1_prepA(
    const float* __restrict__ x, __nv_bfloat16* __restrict__ abf)
{
    int idx = blockIdx.x * 256 + threadIdx.x;           // 0 .. N*128-1
    int m = idx >> 7;
    int kq = (idx & 127) << 2;
    if (m >= N_NODES) return;
    float4 v = *(const float4*)(x + (size_t)m * NFEAT + kq);
    float vv[4] = {v.x, v.y, v.z, v.w};
    __nv_bfloat16 hi[4], lo[4];
#pragma unroll
    for (int i = 0; i < 4; i++) {
        hi[i] = __float2bfloat16(vv[i]);
        lo[i] = __float2bfloat16(vv[i] - __bfloat162float(hi[i]));
    }
    __nv_bfloat16* base = abf + (size_t)m * KCAT + kq;
    *(uint2*)(base)        = *(uint2*)hi;   // seg0: x_hi
    *(uint2*)(base + 512)  = *(uint2*)hi;   // seg1: x_hi
    *(uint2*)(base + 1024) = *(uint2*)lo;   // seg2: x_lo
}

// ---------------------------------------------------------------------------
// P2: build B' bf16 [N][KCAT] = [w_hi | w_lo | w_hi], n = h*64+d
// ---------------------------------------------------------------------------
__global__ __launch_bounds__(256) void p2_prepB(
    const float* __restrict__ W, __nv_bfloat16* __restrict__ bbf)
{
    int idx = blockIdx.x * 256 + threadIdx.x;
    if (idx >= NHID * NFEAT) return;
    int n = idx >> 9;           // output col 0..255
    int k = idx & 511;
    int h = n >> 6, d = n & 63;
    float v = W[((size_t)h * NFEAT + k) * DHEAD + d];
    __nv_bfloat16 hi = __float2bfloat16(v);
    __nv_bfloat16 lo = __float2bfloat16(v - __bfloat162float(hi));
    __nv_bfloat16* base = bbf + (size_t)n * KCAT + k;
    base[0]    = hi;
    base[512]  = lo;
    base[1024] = hi;
}

// ---------------------------------------------------------------------------
// K1: HMMA GEMM  whcat[6144,256] = A'[6144,1536] @ B'[256,1536]^T
//     mma.sync.m16n8k16 bf16, block 128x128, BK=32, 8 warps (4x2),
//     warp tile 32x64. Padded smem (stride 20 u32) -> conflict-free frags.
// ---------------------------------------------------------------------------
#define BK     32
#define SSTR   20              // u32 words per smem row (16 data + 4 pad)

__device__ __forceinline__ void hmma16816(
    float& c0, float& c1, float& c2, float& c3,
    u32 a0, u32 a1, u32 a2, u32 a3, u32 b0, u32 b1)
{
    asm volatile(
        "mma.sync.aligned.m16n8k16.row.col.f32.bf16.bf16.f32 "
        "{%0,%1,%2,%3}, {%4,%5,%6,%7}, {%8,%9}, {%0,%1,%2,%3};\n"
        : "+f"(c0), "+f"(c1), "+f"(c2), "+f"(c3)
        : "r"(a0), "r"(a1), "r"(a2), "r"(a3), "r"(b0), "r"(b1));
}

__global__ __launch_bounds__(256) void k1_mma(
    const __nv_bfloat16* __restrict__ abf, const __nv_bfloat16* __restrict__ bbf,
    float* __restrict__ C)
{
    __shared__ u32 As[128][SSTR];
    __shared__ u32 Bs[128][SSTR];

    const int tid  = threadIdx.x;
    const int wid  = tid >> 5;
    const int lane = tid & 31;
    const int g    = lane >> 2;      // groupID
    const int tig  = lane & 3;       // thread in group
    const int m0   = blockIdx.x * 128;
    const int n0   = blockIdx.y * 128;
    const int wm   = (wid & 3) * 32; // warp m offset within block
    const int wn   = (wid >> 2) * 64;// warp n offset within block

    float acc[2][8][4];
#pragma unroll
    for (int mi = 0; mi < 2; mi++)
#pragma unroll
        for (int ni = 0; ni < 8; ni++)
#pragma unroll
            for (int q = 0; q < 4; q++) acc[mi][ni][q] = 0.f;

    // tile-load mapping: 512 uint4 per tile, 2 per thread
    const int l_row0 = tid >> 2;           // 0..63
    const int l_wq   = (tid & 3) << 2;     // u32 word offset 0/4/8/12

    for (int kk = 0; kk < KCAT; kk += BK) {
#pragma unroll
        for (int it = 0; it < 2; it++) {
            int row = l_row0 + it * 64;
            uint4 va = *(const uint4*)(abf + (size_t)(m0 + row) * KCAT + kk + l_wq * 2);
            *(uint4*)&As[row][l_wq] = va;
            uint4 vb = *(const uint4*)(bbf + (size_t)(n0 + row) * KCAT + kk + l_wq * 2);
            *(uint4*)&Bs[row][l_wq] = vb;
        }
        __syncthreads();

#pragma unroll
        for (int ks = 0; ks < 2; ks++) {
            const int kw = ks * 8;           // word offset for this k16 step
            u32 a[2][4];
#pragma unroll
            for (int mi = 0; mi < 2; mi++) {
                const int r = wm + mi * 16;
                a[mi][0] = As[r + g    ][kw + tig];
                a[mi][1] = As[r + g + 8][kw + tig];
                a[mi][2] = As[r + g    ][kw + tig + 4];
                a[mi][3] = As[r + g + 8][kw + tig + 4];
            }
            u32 b[8][2];
#pragma unroll
            for (int ni = 0; ni < 8; ni++) {
                const int n = wn + ni * 8 + g;
                b[ni][0] = Bs[n][kw + tig];
                b[ni][1] = Bs[n][kw + tig + 4];
            }
#pragma unroll
            for (int mi = 0; mi < 2; mi++)
#pragma unroll
                for (int ni = 0; ni < 8; ni++)
                    hmma16816(acc[mi][ni][0], acc[mi][ni][1],
                              acc[mi][ni][2], acc[mi][ni][3],
                              a[mi][0], a[mi][1], a[mi][2], a[mi][3],
                              b[ni][0], b[ni][1]);
        }
        __syncthreads();
    }

    // epilogue
#pragma unroll
    for (int mi = 0; mi < 2; mi++) {
        const int r0 = m0 + wm + mi * 16 + g;
#pragma unroll
        for (int ni = 0; ni < 8; ni++) {
            const int c0 = n0 + wn + ni * 8 + tig * 2;
            *(float2*)(C + (size_t)r0 * NHID + c0) =
                make_float2(acc[mi][ni][0], acc[mi][ni][1]);
            *(float2*)(C + (size_t)(r0 + 8) * NHID + c0) =
                make_float2(acc[mi][ni][2], acc[mi][ni][3]);
        }
    }
}

// ---------------------------------------------------------------------------
// K2: s/t per (head, node)
// ---------------------------------------------------------------------------
__global__ __launch_bounds__(256) void k2_st(
    const float* __restrict__ wh, const float* __restrict__ a_src,
    const float* __restrict__ a_dst,
    float* __restrict__ s, float* __restrict__ t)
{
    int id = blockIdx.x * blockDim.x + threadIdx.x;
    if (id >= NHEADS * N_NODES) return;
    int h = id / N_NODES;
    int i = id - h * N_NODES;
    const float* row = wh + (size_t)i * NHID + h * DHEAD;
    const float* as  = a_src + h * DHEAD;
    const float* ad  = a_dst + h * DHEAD;
    float ss = 0.f, tt = 0.f;
#pragma unroll 8
    for (int d = 0; d < DHEAD; d++) {
        float v = row[d];
        ss += v * as[d];
        tt += v * ad[d];
    }
    s[id] = ss;
    t[id] = tt;
}

// ---------------------------------------------------------------------------
// K3: fused compaction + sparse softmax + aggregation + ELU
// ---------------------------------------------------------------------------
__global__ __launch_bounds__(256) void k3_attn(
    const int* __restrict__ adj, const float* __restrict__ wh,
    const float* __restrict__ s, const float* __restrict__ t,
    float* __restrict__ hcat)
{
    __shared__ int   sidx[MAXDEG];
    __shared__ float sw[NHEADS * MAXDEG];
    __shared__ float srs[NHEADS];
    __shared__ int   scount;

    const int i   = blockIdx.x;
    const int tid = threadIdx.x;
    if (tid == 0) scount = 0;
    __syncthreads();

    const int4* arow = (const int4*)(adj + (size_t)i * N_NODES);
    for (int q = tid; q < N_NODES / 4; q += 256) {
        int4 v = arow[q];
        if (v.x) { int p = atomicAdd(&scount, 1); if (p < MAXDEG) sidx[p] = q * 4 + 0; }
        if (v.y) { int p = atomicAdd(&scount, 1); if (p < MAXDEG) sidx[p] = q * 4 + 1; }
        if (v.z) { int p = atomicAdd(&scount, 1); if (p < MAXDEG) sidx[p] = q * 4 + 2; }
        if (v.w) { int p = atomicAdd(&scount, 1); if (p < MAXDEG) sidx[p] = q * 4 + 3; }
    }
    __syncthreads();
    const int deg = min(scount, MAXDEG);

    for (int m = tid; m < deg * NHEADS; m += 256) {
        int j = m >> 2;
        int h = m & 3;
        int jj = sidx[j];
        float e = s[h * N_NODES + i] + t[h * N_NODES + jj];
        e = e > 0.f ? e : LRELU_ALPHA * e;
        sw[h * MAXDEG + j] = e;
    }
    __syncthreads();

    const int warp = tid >> 5;
    const int lane = tid & 31;
    if (warp < NHEADS) {
        const int h = warp;
        float mx = -3.4e38f;
        for (int j = lane; j < deg; j += 32) mx = fmaxf(mx, sw[h * MAXDEG + j]);
#pragma unroll
        for (int o = 16; o; o >>= 1) mx = fmaxf(mx, __shfl_xor_sync(0xffffffffu, mx, o));
        float sum = 0.f;
        for (int j = lane; j < deg; j += 32) {
            float w = __expf(sw[h * MAXDEG + j] - mx);
            sw[h * MAXDEG + j] = w;
            sum += w;
        }
#pragma unroll
        for (int o = 16; o; o >>= 1) sum += __shfl_xor_sync(0xffffffffu, sum, o);
        if (lane == 0) srs[h] = (sum > 0.f) ? 1.f / sum : 0.f;
    }
    __syncthreads();

    const int h = tid >> 6;
    float acc = 0.f;
    const float* whb = wh + tid;
#pragma unroll 4
    for (int j = 0; j < deg; j++) {
        int jj = sidx[j];
        acc += sw[h * MAXDEG + j] * whb[(size_t)jj * NHID];
    }
    acc *= srs[h];
    acc = acc > 0.f ? acc : (__expf(acc) - 1.f);
    hcat[(size_t)i * NHID + tid] = acc;
}

// ---------------------------------------------------------------------------
// K4: out = elu(hcat @ lin_w^T + b)  (scalar, known-good)
// ---------------------------------------------------------------------------
__global__ __launch_bounds__(256) void k4_out(
    const float* __restrict__ hcat, const float* __restrict__ lin_w,
    const float* __restrict__ lin_b, float* __restrict__ out)
{
    __shared__ float As4[16][64];
    __shared__ float Bs4[16][64];

    const int m0 = blockIdx.x * 64;
    const int n0 = blockIdx.y * 64;
    const int t  = threadIdx.x;
    const int tx = t & 15;
    const int ty = t >> 4;

    float acc[4][4];
#pragma unroll
    for (int i = 0; i < 4; i++)
#pragma unroll
        for (int j = 0; j < 4; j++) acc[i][j] = 0.f;

    const int l_row = t >> 2;
    const int l_kq  = t & 3;

    for (int kk = 0; kk < NHID; kk += 16) {
        float4 av = *(const float4*)(hcat + (size_t)(m0 + l_row) * NHID + kk + l_kq * 4);
        As4[l_kq * 4 + 0][l_row] = av.x;
        As4[l_kq * 4 + 1][l_row] = av.y;
        As4[l_kq * 4 + 2][l_row] = av.z;
        As4[l_kq * 4 + 3][l_row] = av.w;
        float4 bv = *(const float4*)(lin_w + (size_t)(n0 + l_row) * NHID + kk + l_kq * 4);
        Bs4[l_kq * 4 + 0][l_row] = bv.x;
        Bs4[l_kq * 4 + 1][l_row] = bv.y;
        Bs4[l_kq * 4 + 2][l_row] = bv.z;
        Bs4[l_kq * 4 + 3][l_row] = bv.w;
        __syncthreads();

#pragma unroll
        for (int k = 0; k < 16; k++) {
            float a[4], b[4];
            *(float4*)a = *(const float4*)&As4[k][ty * 4];
            *(float4*)b = *(const float4*)&Bs4[k][tx * 4];
#pragma unroll
            for (int i = 0; i < 4; i++)
#pragma unroll
                for (int j = 0; j < 4; j++)
                    acc[i][j] += a[i] * b[j];
        }
        __syncthreads();
    }

#pragma unroll
    for (int i = 0; i < 4; i++) {
#pragma unroll
        for (int j = 0; j < 4; j++) {
            float v = acc[i][j] + lin_b[n0 + tx * 4 + j];
            v = v > 0.f ? v : (__expf(v) - 1.f);
            out[(size_t)(m0 + ty * 4 + i) * NEMBED + n0 + tx * 4 + j] = v;
        }
    }
}

// ---------------------------------------------------------------------------
extern "C" void kernel_launch(void* const* d_in, const int* in_sizes, int n_in,
                              void* d_out, int out_size)
{
    const float* x     = (const float*)d_in[0];
    const int*   adj   = (const int*)  d_in[1];
    const float* W     = (const float*)d_in[2];
    const float* a_src = (const float*)d_in[3];
    const float* a_dst = (const float*)d_in[4];
    const float* lin_w = (const float*)d_in[5];
    const float* lin_b = (const float*)d_in[6];
    float* out = (float*)d_out;

    float* whcat; cudaGetSymbolAddress((void**)&whcat, g_whcat);
    float* s;     cudaGetSymbolAddress((void**)&s, g_s);
    float* t;     cudaGetSymbolAddress((void**)&t, g_t);
    float* hcat;  cudaGetSymbolAddress((void**)&hcat, g_hcat);
    __nv_bfloat16* abf; cudaGetSymbolAddress((void**)&abf, g_abf);
    __nv_bfloat16* bbf; cudaGetSymbolAddress((void**)&bbf, g_bbf);

    p1_prepA<<<(N_NODES * 128 + 255) / 256, 256>>>(x, abf);
    p2_prepB<<<(NHID * NFEAT + 255) / 256, 256>>>(W, bbf);

    dim3 g1(N_NODES / 128, NHID / 128);
    k1_mma<<<g1, 256>>>(abf, bbf, whcat);

    k2_st<<<(NHEADS * N_NODES + 255) / 256, 256>>>(whcat, a_src, a_dst, s, t);

    k3_attn<<<N_NODES, 256>>>(adj, whcat, s, t, hcat);

    dim3 g4(N_NODES / 64, NEMBED / 64);
    k4_out<<<g4, 256>>>(hcat, lin_w, lin_b, out);
}

// round 5
// speedup vs baseline: 1.3676x; 1.0717x over previous
#include <cuda_runtime.h>
#include <cuda_bf16.h>

#define N_NODES 6144
#define NFEAT   512
#define NHID    256
#define NHEADS  4
#define DHEAD   64
#define NEMBED  128
#define LRELU_ALPHA 0.2f
#define MAXDEG  256
#define KCAT    1536           // 3 * NFEAT (split-bf16 concat, k1)
#define KCAT4   768            // 3 * NHID  (split-bf16 concat, k4)

typedef unsigned int u32;

// Scratch (device globals; no runtime allocation allowed)
__device__ float g_whcat[N_NODES * NHID];
__device__ float g_s[NHEADS * N_NODES];
__device__ float g_t[NHEADS * N_NODES];
__device__ __nv_bfloat16 g_abf[N_NODES * KCAT];   // [x_hi | x_hi | x_lo]
__device__ __nv_bfloat16 g_bbf[NHID * KCAT];      // [w_hi | w_lo | w_hi]
__device__ __nv_bfloat16 g_h4a[N_NODES * KCAT4];  // [h_hi | h_hi | h_lo]
__device__ __nv_bfloat16 g_b4[NEMBED * KCAT4];    // [w_hi | w_lo | w_hi]

// ---------------------------------------------------------------------------
__device__ __forceinline__ void hmma16816(
    float& c0, float& c1, float& c2, float& c3,
    u32 a0, u32 a1, u32 a2, u32 a3, u32 b0, u32 b1)
{
    asm volatile(
        "mma.sync.aligned.m16n8k16.row.col.f32.bf16.bf16.f32 "
        "{%0,%1,%2,%3}, {%4,%5,%6,%7}, {%8,%9}, {%0,%1,%2,%3};\n"
        : "+f"(c0), "+f"(c1), "+f"(c2), "+f"(c3)
        : "r"(a0), "r"(a1), "r"(a2), "r"(a3), "r"(b0), "r"(b1));
}

// ---------------------------------------------------------------------------
// P1: build A' bf16  [x_hi | x_hi | x_lo]
// ---------------------------------------------------------------------------
__global__ __launch_bounds__(256) void p1_prepA(
    const float* __restrict__ x, __nv_bfloat16* __restrict__ abf)
{
    int idx = blockIdx.x * 256 + threadIdx.x;
    int m = idx >> 7;
    int kq = (idx & 127) << 2;
    if (m >= N_NODES) return;
    float4 v = *(const float4*)(x + (size_t)m * NFEAT + kq);
    float vv[4] = {v.x, v.y, v.z, v.w};
    __nv_bfloat16 hi[4], lo[4];
#pragma unroll
    for (int i = 0; i < 4; i++) {
        hi[i] = __float2bfloat16(vv[i]);
        lo[i] = __float2bfloat16(vv[i] - __bfloat162float(hi[i]));
    }
    __nv_bfloat16* base = abf + (size_t)m * KCAT + kq;
    *(uint2*)(base)        = *(uint2*)hi;
    *(uint2*)(base + 512)  = *(uint2*)hi;
    *(uint2*)(base + 1024) = *(uint2*)lo;
}

// ---------------------------------------------------------------------------
// P2: build B' bf16 [256][KCAT] = [w_hi | w_lo | w_hi], n = h*64+d
// ---------------------------------------------------------------------------
__global__ __launch_bounds__(256) void p2_prepB(
    const float* __restrict__ W, __nv_bfloat16* __restrict__ bbf)
{
    int idx = blockIdx.x * 256 + threadIdx.x;
    if (idx >= NHID * NFEAT) return;
    int n = idx >> 9;
    int k = idx & 511;
    int h = n >> 6, d = n & 63;
    float v = W[((size_t)h * NFEAT + k) * DHEAD + d];
    __nv_bfloat16 hi = __float2bfloat16(v);
    __nv_bfloat16 lo = __float2bfloat16(v - __bfloat162float(hi));
    __nv_bfloat16* base = bbf + (size_t)n * KCAT + k;
    base[0]    = hi;
    base[512]  = lo;
    base[1024] = hi;
}

// ---------------------------------------------------------------------------
// P3: build lin_w' bf16 [128][KCAT4] = [w_hi | w_lo | w_hi]
// ---------------------------------------------------------------------------
__global__ __launch_bounds__(256) void p3_prepL(
    const float* __restrict__ lin_w, __nv_bfloat16* __restrict__ b4)
{
    int idx = blockIdx.x * 256 + threadIdx.x;
    if (idx >= NEMBED * NHID) return;
    int n = idx >> 8;
    int k = idx & 255;
    float v = lin_w[(size_t)n * NHID + k];
    __nv_bfloat16 hi = __float2bfloat16(v);
    __nv_bfloat16 lo = __float2bfloat16(v - __bfloat162float(hi));
    __nv_bfloat16* base = b4 + (size_t)n * KCAT4 + k;
    base[0]   = hi;
    base[256] = lo;
    base[512] = hi;
}

// ---------------------------------------------------------------------------
// K1: HMMA GEMM  whcat[6144,256] = A'[6144,1536] @ B'[256,1536]^T
// ---------------------------------------------------------------------------
#define BK     32
#define SSTR   20

__global__ __launch_bounds__(256) void k1_mma(
    const __nv_bfloat16* __restrict__ abf, const __nv_bfloat16* __restrict__ bbf,
    float* __restrict__ C)
{
    __shared__ u32 As[128][SSTR];
    __shared__ u32 Bs[128][SSTR];

    const int tid  = threadIdx.x;
    const int wid  = tid >> 5;
    const int lane = tid & 31;
    const int g    = lane >> 2;
    const int tig  = lane & 3;
    const int m0   = blockIdx.x * 128;
    const int n0   = blockIdx.y * 128;
    const int wm   = (wid & 3) * 32;
    const int wn   = (wid >> 2) * 64;

    float acc[2][8][4];
#pragma unroll
    for (int mi = 0; mi < 2; mi++)
#pragma unroll
        for (int ni = 0; ni < 8; ni++)
#pragma unroll
            for (int q = 0; q < 4; q++) acc[mi][ni][q] = 0.f;

    const int l_row0 = tid >> 2;
    const int l_wq   = (tid & 3) << 2;

    for (int kk = 0; kk < KCAT; kk += BK) {
#pragma unroll
        for (int it = 0; it < 2; it++) {
            int row = l_row0 + it * 64;
            uint4 va = *(const uint4*)(abf + (size_t)(m0 + row) * KCAT + kk + l_wq * 2);
            *(uint4*)&As[row][l_wq] = va;
            uint4 vb = *(const uint4*)(bbf + (size_t)(n0 + row) * KCAT + kk + l_wq * 2);
            *(uint4*)&Bs[row][l_wq] = vb;
        }
        __syncthreads();

#pragma unroll
        for (int ks = 0; ks < 2; ks++) {
            const int kw = ks * 8;
            u32 a[2][4];
#pragma unroll
            for (int mi = 0; mi < 2; mi++) {
                const int r = wm + mi * 16;
                a[mi][0] = As[r + g    ][kw + tig];
                a[mi][1] = As[r + g + 8][kw + tig];
                a[mi][2] = As[r + g    ][kw + tig + 4];
                a[mi][3] = As[r + g + 8][kw + tig + 4];
            }
            u32 b[8][2];
#pragma unroll
            for (int ni = 0; ni < 8; ni++) {
                const int n = wn + ni * 8 + g;
                b[ni][0] = Bs[n][kw + tig];
                b[ni][1] = Bs[n][kw + tig + 4];
            }
#pragma unroll
            for (int mi = 0; mi < 2; mi++)
#pragma unroll
                for (int ni = 0; ni < 8; ni++)
                    hmma16816(acc[mi][ni][0], acc[mi][ni][1],
                              acc[mi][ni][2], acc[mi][ni][3],
                              a[mi][0], a[mi][1], a[mi][2], a[mi][3],
                              b[ni][0], b[ni][1]);
        }
        __syncthreads();
    }

#pragma unroll
    for (int mi = 0; mi < 2; mi++) {
        const int r0 = m0 + wm + mi * 16 + g;
#pragma unroll
        for (int ni = 0; ni < 8; ni++) {
            const int c0 = n0 + wn + ni * 8 + tig * 2;
            *(float2*)(C + (size_t)r0 * NHID + c0) =
                make_float2(acc[mi][ni][0], acc[mi][ni][1]);
            *(float2*)(C + (size_t)(r0 + 8) * NHID + c0) =
                make_float2(acc[mi][ni][2], acc[mi][ni][3]);
        }
    }
}

// ---------------------------------------------------------------------------
// K2: coalesced s/t — one warp per node, segmented reduce over 8-lane groups.
// ---------------------------------------------------------------------------
__global__ __launch_bounds__(256) void k2_st(
    const float* __restrict__ wh, const float* __restrict__ a_src,
    const float* __restrict__ a_dst,
    float* __restrict__ s, float* __restrict__ t)
{
    __shared__ float asf[NHID], adf[NHID];
    const int tid = threadIdx.x;
    if (tid < NHID) {          // a_src[h][d] flat at h*64+d
        asf[tid] = a_src[tid];
        adf[tid] = a_dst[tid];
    }
    __syncthreads();

    const int wid  = tid >> 5;
    const int lane = tid & 31;
    const int node = blockIdx.x * 8 + wid;
    if (node >= N_NODES) return;

    const float* row = wh + (size_t)node * NHID + lane * 8;
    float4 v0 = *(const float4*)(row + 0);
    float4 v1 = *(const float4*)(row + 4);
    const float* as = asf + lane * 8;
    const float* ad = adf + lane * 8;
    float ss = v0.x * as[0] + v0.y * as[1] + v0.z * as[2] + v0.w * as[3]
             + v1.x * as[4] + v1.y * as[5] + v1.z * as[6] + v1.w * as[7];
    float tt = v0.x * ad[0] + v0.y * ad[1] + v0.z * ad[2] + v0.w * ad[3]
             + v1.x * ad[4] + v1.y * ad[5] + v1.z * ad[6] + v1.w * ad[7];
#pragma unroll
    for (int o = 4; o; o >>= 1) {
        ss += __shfl_xor_sync(0xffffffffu, ss, o);
        tt += __shfl_xor_sync(0xffffffffu, tt, o);
    }
    if ((lane & 7) == 0) {
        int h = lane >> 3;
        s[h * N_NODES + node] = ss;
        t[h * N_NODES + node] = tt;
    }
}

// ---------------------------------------------------------------------------
// K3: fused compaction + sparse softmax + aggregation + ELU.
//     Output written directly as split-bf16 concat layout for K4.
// ---------------------------------------------------------------------------
__global__ __launch_bounds__(256) void k3_attn(
    const int* __restrict__ adj, const float* __restrict__ wh,
    const float* __restrict__ s, const float* __restrict__ t,
    __nv_bfloat16* __restrict__ h4a)
{
    __shared__ int   sidx[MAXDEG];
    __shared__ float sw[NHEADS * MAXDEG];
    __shared__ float srs[NHEADS];
    __shared__ int   scount;

    const int i   = blockIdx.x;
    const int tid = threadIdx.x;
    if (tid == 0) scount = 0;
    __syncthreads();

    const int4* arow = (const int4*)(adj + (size_t)i * N_NODES);
    for (int q = tid; q < N_NODES / 4; q += 256) {
        int4 v = arow[q];
        if (v.x) { int p = atomicAdd(&scount, 1); if (p < MAXDEG) sidx[p] = q * 4 + 0; }
        if (v.y) { int p = atomicAdd(&scount, 1); if (p < MAXDEG) sidx[p] = q * 4 + 1; }
        if (v.z) { int p = atomicAdd(&scount, 1); if (p < MAXDEG) sidx[p] = q * 4 + 2; }
        if (v.w) { int p = atomicAdd(&scount, 1); if (p < MAXDEG) sidx[p] = q * 4 + 3; }
    }
    __syncthreads();
    const int deg = min(scount, MAXDEG);

    for (int m = tid; m < deg * NHEADS; m += 256) {
        int j = m >> 2;
        int h = m & 3;
        int jj = sidx[j];
        float e = s[h * N_NODES + i] + t[h * N_NODES + jj];
        e = e > 0.f ? e : LRELU_ALPHA * e;
        sw[h * MAXDEG + j] = e;
    }
    __syncthreads();

    const int warp = tid >> 5;
    const int lane = tid & 31;
    if (warp < NHEADS) {
        const int h = warp;
        float mx = -3.4e38f;
        for (int j = lane; j < deg; j += 32) mx = fmaxf(mx, sw[h * MAXDEG + j]);
#pragma unroll
        for (int o = 16; o; o >>= 1) mx = fmaxf(mx, __shfl_xor_sync(0xffffffffu, mx, o));
        float sum = 0.f;
        for (int j = lane; j < deg; j += 32) {
            float w = __expf(sw[h * MAXDEG + j] - mx);
            sw[h * MAXDEG + j] = w;
            sum += w;
        }
#pragma unroll
        for (int o = 16; o; o >>= 1) sum += __shfl_xor_sync(0xffffffffu, sum, o);
        if (lane == 0) srs[h] = (sum > 0.f) ? 1.f / sum : 0.f;
    }
    __syncthreads();

    const int h = tid >> 6;
    float acc = 0.f;
    const float* whb = wh + tid;
#pragma unroll 4
    for (int j = 0; j < deg; j++) {
        int jj = sidx[j];
        acc += sw[h * MAXDEG + j] * whb[(size_t)jj * NHID];
    }
    acc *= srs[h];
    acc = acc > 0.f ? acc : (__expf(acc) - 1.f);

    __nv_bfloat16 hi = __float2bfloat16(acc);
    __nv_bfloat16 lo = __float2bfloat16(acc - __bfloat162float(hi));
    __nv_bfloat16* base = h4a + (size_t)i * KCAT4 + tid;
    base[0]   = hi;
    base[256] = hi;
    base[512] = lo;
}

// ---------------------------------------------------------------------------
// K4: HMMA GEMM  out = elu(h' @ lin_w'^T + b)
//     M=6144, N=128, K=768.  BM=32, BN=128 (full N), BK=32, 192 blocks.
//     8 warps, warp tile 32x16 (mi=2, ni=2), wn = wid*16.
// ---------------------------------------------------------------------------
__global__ __launch_bounds__(256) void k4_mma(
    const __nv_bfloat16* __restrict__ h4a, const __nv_bfloat16* __restrict__ b4,
    const float* __restrict__ lin_b, float* __restrict__ out)
{
    __shared__ u32 As[32][SSTR];
    __shared__ u32 Bs[128][SSTR];

    const int tid  = threadIdx.x;
    const int wid  = tid >> 5;
    const int lane = tid & 31;
    const int g    = lane >> 2;
    const int tig  = lane & 3;
    const int m0   = blockIdx.x * 32;
    const int wn   = wid * 16;

    float acc[2][2][4];
#pragma unroll
    for (int mi = 0; mi < 2; mi++)
#pragma unroll
        for (int ni = 0; ni < 2; ni++)
#pragma unroll
            for (int q = 0; q < 4; q++) acc[mi][ni][q] = 0.f;

    const int l_row = tid >> 2;           // 0..63
    const int l_wq  = (tid & 3) << 2;

    for (int kk = 0; kk < KCAT4; kk += BK) {
        if (tid < 128) {
            uint4 va = *(const uint4*)(h4a + (size_t)(m0 + l_row) * KCAT4 + kk + l_wq * 2);
            *(uint4*)&As[l_row][l_wq] = va;
        }
#pragma unroll
        for (int it = 0; it < 2; it++) {
            int row = l_row + it * 64;
            uint4 vb = *(const uint4*)(b4 + (size_t)row * KCAT4 + kk + l_wq * 2);
            *(uint4*)&Bs[row][l_wq] = vb;
        }
        __syncthreads();

#pragma unroll
        for (int ks = 0; ks < 2; ks++) {
            const int kw = ks * 8;
            u32 a[2][4];
#pragma unroll
            for (int mi = 0; mi < 2; mi++) {
                const int r = mi * 16;
                a[mi][0] = As[r + g    ][kw + tig];
                a[mi][1] = As[r + g + 8][kw + tig];
                a[mi][2] = As[r + g    ][kw + tig + 4];
                a[mi][3] = As[r + g + 8][kw + tig + 4];
            }
            u32 b[2][2];
#pragma unroll
            for (int ni = 0; ni < 2; ni++) {
                const int n = wn + ni * 8 + g;
                b[ni][0] = Bs[n][kw + tig];
                b[ni][1] = Bs[n][kw + tig + 4];
            }
#pragma unroll
            for (int mi = 0; mi < 2; mi++)
#pragma unroll
                for (int ni = 0; ni < 2; ni++)
                    hmma16816(acc[mi][ni][0], acc[mi][ni][1],
                              acc[mi][ni][2], acc[mi][ni][3],
                              a[mi][0], a[mi][1], a[mi][2], a[mi][3],
                              b[ni][0], b[ni][1]);
        }
        __syncthreads();
    }

#pragma unroll
    for (int mi = 0; mi < 2; mi++) {
        const int r0 = m0 + mi * 16 + g;
#pragma unroll
        for (int ni = 0; ni < 2; ni++) {
            const int c0 = wn + ni * 8 + tig * 2;
            float b0 = lin_b[c0], b1 = lin_b[c0 + 1];
            float v0 = acc[mi][ni][0] + b0;
            float v1 = acc[mi][ni][1] + b1;
            float v2 = acc[mi][ni][2] + b0;
            float v3 = acc[mi][ni][3] + b1;
            v0 = v0 > 0.f ? v0 : (__expf(v0) - 1.f);
            v1 = v1 > 0.f ? v1 : (__expf(v1) - 1.f);
            v2 = v2 > 0.f ? v2 : (__expf(v2) - 1.f);
            v3 = v3 > 0.f ? v3 : (__expf(v3) - 1.f);
            *(float2*)(out + (size_t)r0 * NEMBED + c0) = make_float2(v0, v1);
            *(float2*)(out + (size_t)(r0 + 8) * NEMBED + c0) = make_float2(v2, v3);
        }
    }
}

// ---------------------------------------------------------------------------
extern "C" void kernel_launch(void* const* d_in, const int* in_sizes, int n_in,
                              void* d_out, int out_size)
{
    const float* x     = (const float*)d_in[0];
    const int*   adj   = (const int*)  d_in[1];
    const float* W     = (const float*)d_in[2];
    const float* a_src = (const float*)d_in[3];
    const float* a_dst = (const float*)d_in[4];
    const float* lin_w = (const float*)d_in[5];
    const float* lin_b = (const float*)d_in[6];
    float* out = (float*)d_out;

    float* whcat; cudaGetSymbolAddress((void**)&whcat, g_whcat);
    float* s;     cudaGetSymbolAddress((void**)&s, g_s);
    float* t;     cudaGetSymbolAddress((void**)&t, g_t);
    __nv_bfloat16* abf; cudaGetSymbolAddress((void**)&abf, g_abf);
    __nv_bfloat16* bbf; cudaGetSymbolAddress((void**)&bbf, g_bbf);
    __nv_bfloat16* h4a; cudaGetSymbolAddress((void**)&h4a, g_h4a);
    __nv_bfloat16* b4;  cudaGetSymbolAddress((void**)&b4, g_b4);

    p1_prepA<<<(N_NODES * 128 + 255) / 256, 256>>>(x, abf);
    p2_prepB<<<(NHID * NFEAT + 255) / 256, 256>>>(W, bbf);
    p3_prepL<<<(NEMBED * NHID + 255) / 256, 256>>>(lin_w, b4);

    dim3 g1(N_NODES / 128, NHID / 128);
    k1_mma<<<g1, 256>>>(abf, bbf, whcat);

    k2_st<<<N_NODES / 8, 256>>>(whcat, a_src, a_dst, s, t);

    k3_attn<<<N_NODES, 256>>>(adj, whcat, s, t, h4a);

    k4_mma<<<N_NODES / 32, 256>>>(h4a, b4, lin_b, out);
}

// round 6
// speedup vs baseline: 1.5045x; 1.1000x over previous
#include <cuda_runtime.h>
#include <cuda_bf16.h>

#define N_NODES 6144
#define NFEAT   512
#define NHID    256
#define NHEADS  4
#define DHEAD   64
#define NEMBED  128
#define LRELU_ALPHA 0.2f
#define MAXDEG  256
#define KCAT    1536           // 3 * NFEAT (split-bf16 concat, k1)
#define KCAT4   768            // 3 * NHID  (split-bf16 concat, k4)

typedef unsigned int u32;

// Scratch (device globals; no runtime allocation allowed)
__device__ float g_whcat[N_NODES * NHID];
__device__ float g_s[NHEADS * N_NODES];
__device__ float g_t[NHEADS * N_NODES];
__device__ __nv_bfloat16 g_abf[N_NODES * KCAT];   // [x_hi | x_hi | x_lo]
__device__ __nv_bfloat16 g_bbf[NHID * KCAT];      // [w_hi | w_lo | w_hi]
__device__ __nv_bfloat16 g_h4a[N_NODES * KCAT4];  // [h_hi | h_hi | h_lo]
__device__ __nv_bfloat16 g_b4[NEMBED * KCAT4];    // [w_hi | w_lo | w_hi]

// ---------------------------------------------------------------------------
__device__ __forceinline__ void hmma16816(
    float& c0, float& c1, float& c2, float& c3,
    u32 a0, u32 a1, u32 a2, u32 a3, u32 b0, u32 b1)
{
    asm volatile(
        "mma.sync.aligned.m16n8k16.row.col.f32.bf16.bf16.f32 "
        "{%0,%1,%2,%3}, {%4,%5,%6,%7}, {%8,%9}, {%0,%1,%2,%3};\n"
        : "+f"(c0), "+f"(c1), "+f"(c2), "+f"(c3)
        : "r"(a0), "r"(a1), "r"(a2), "r"(a3), "r"(b0), "r"(b1));
}
__device__ __forceinline__ void ldsm4(u32& r0, u32& r1, u32& r2, u32& r3, u32 addr)
{
    asm volatile("ldmatrix.sync.aligned.m8n8.x4.shared.b16 {%0,%1,%2,%3}, [%4];"
                 : "=r"(r0), "=r"(r1), "=r"(r2), "=r"(r3) : "r"(addr));
}
__device__ __forceinline__ void cp16(u32 saddr, const void* gptr)
{
    asm volatile("cp.async.cg.shared.global [%0], [%1], 16;" :: "r"(saddr), "l"(gptr));
}
#define CP_COMMIT() asm volatile("cp.async.commit_group;" ::: "memory")
#define CP_WAIT0()  asm volatile("cp.async.wait_group 0;" ::: "memory")
#define CP_WAIT1()  asm volatile("cp.async.wait_group 1;" ::: "memory")

__device__ __forceinline__ u32 smem_u32(const void* p)
{
    u32 a;
    asm("{ .reg .u64 t; cvta.to.shared.u64 t, %1; cvt.u32.u64 %0, t; }"
        : "=r"(a) : "l"(p));
    return a;
}

// ---------------------------------------------------------------------------
// P1: build A' bf16  [x_hi | x_hi | x_lo]
// ---------------------------------------------------------------------------
__global__ __launch_bounds__(256) void p1_prepA(
    const float* __restrict__ x, __nv_bfloat16* __restrict__ abf)
{
    int idx = blockIdx.x * 256 + threadIdx.x;
    int m = idx >> 7;
    int kq = (idx & 127) << 2;
    if (m >= N_NODES) return;
    float4 v = *(const float4*)(x + (size_t)m * NFEAT + kq);
    float vv[4] = {v.x, v.y, v.z, v.w};
    __nv_bfloat16 hi[4], lo[4];
#pragma unroll
    for (int i = 0; i < 4; i++) {
        hi[i] = __float2bfloat16(vv[i]);
        lo[i] = __float2bfloat16(vv[i] - __bfloat162float(hi[i]));
    }
    __nv_bfloat16* base = abf + (size_t)m * KCAT + kq;
    *(uint2*)(base)        = *(uint2*)hi;
    *(uint2*)(base + 512)  = *(uint2*)hi;
    *(uint2*)(base + 1024) = *(uint2*)lo;
}

// ---------------------------------------------------------------------------
// P2: build B' bf16 [256][KCAT] = [w_hi | w_lo | w_hi], n = h*64+d
// ---------------------------------------------------------------------------
__global__ __launch_bounds__(256) void p2_prepB(
    const float* __restrict__ W, __nv_bfloat16* __restrict__ bbf)
{
    int idx = blockIdx.x * 256 + threadIdx.x;
    if (idx >= NHID * NFEAT) return;
    int n = idx >> 9;
    int k = idx & 511;
    int h = n >> 6, d = n & 63;
    float v = W[((size_t)h * NFEAT + k) * DHEAD + d];
    __nv_bfloat16 hi = __float2bfloat16(v);
    __nv_bfloat16 lo = __float2bfloat16(v - __bfloat162float(hi));
    __nv_bfloat16* base = bbf + (size_t)n * KCAT + k;
    base[0]    = hi;
    base[512]  = lo;
    base[1024] = hi;
}

// ---------------------------------------------------------------------------
// P3: build lin_w' bf16 [128][KCAT4] = [w_hi | w_lo | w_hi]
// ---------------------------------------------------------------------------
__global__ __launch_bounds__(256) void p3_prepL(
    const float* __restrict__ lin_w, __nv_bfloat16* __restrict__ b4)
{
    int idx = blockIdx.x * 256 + threadIdx.x;
    if (idx >= NEMBED * NHID) return;
    int n = idx >> 8;
    int k = idx & 255;
    float v = lin_w[(size_t)n * NHID + k];
    __nv_bfloat16 hi = __float2bfloat16(v);
    __nv_bfloat16 lo = __float2bfloat16(v - __bfloat162float(hi));
    __nv_bfloat16* base = b4 + (size_t)n * KCAT4 + k;
    base[0]   = hi;
    base[256] = lo;
    base[512] = hi;
}

// ---------------------------------------------------------------------------
// K1: HMMA GEMM  whcat[6144,256] = A'[6144,1536] @ B'[256,1536]^T
//     BM=64, BN=128, BK=32, 192 blocks, 8 warps (2x4), warp tile 32x32.
//     cp.async 2-stage double buffer + ldmatrix fragment loads.
// ---------------------------------------------------------------------------
#define BK     32
#define SSTR   20              // u32 words per smem row (16 data + 4 pad)
#define K1_NIT (KCAT / BK)     // 48

__global__ __launch_bounds__(256) void k1_mma(
    const __nv_bfloat16* __restrict__ abf, const __nv_bfloat16* __restrict__ bbf,
    float* __restrict__ C)
{
    __shared__ u32 As[2][64][SSTR];
    __shared__ u32 Bs[2][128][SSTR];

    const int tid  = threadIdx.x;
    const int wid  = tid >> 5;
    const int lane = tid & 31;
    const int g    = lane >> 2;
    const int tig  = lane & 3;
    const int m0   = blockIdx.x * 64;
    const int n0   = blockIdx.y * 128;
    const int wm   = (wid & 1) * 32;
    const int wn   = (wid >> 1) * 32;

    const u32 sA = smem_u32(As);
    const u32 sB = smem_u32(Bs);

    float acc[2][4][4];
#pragma unroll
    for (int mi = 0; mi < 2; mi++)
#pragma unroll
        for (int ni = 0; ni < 4; ni++)
#pragma unroll
            for (int q = 0; q < 4; q++) acc[mi][ni][q] = 0.f;

    // load mapping: thread -> (row = tid>>2, word-quad = (tid&3)*4)
    const int l_row = tid >> 2;            // 0..63
    const int l_wq  = (tid & 3) << 2;      // u32 word offset
    const int l_col = l_wq << 1;           // bf16 col offset

    // ldmatrix lane address components
    const u32 a_frag_off = ((u32)(wm + (lane & 15)) * SSTR + ((lane >> 4) << 2)) << 2;
    const u32 b_frag_off = ((u32)(wn + (lane & 7) + ((lane >> 4) << 3)) * SSTR
                            + (((lane >> 3) & 1) << 2)) << 2;

    // ---- prologue: stage 0
    {
        cp16(sA + ((0 * 64 + l_row) * SSTR + l_wq) * 4,
             abf + (size_t)(m0 + l_row) * KCAT + l_col);
        cp16(sB + ((0 * 128 + l_row) * SSTR + l_wq) * 4,
             bbf + (size_t)(n0 + l_row) * KCAT + l_col);
        cp16(sB + ((0 * 128 + 64 + l_row) * SSTR + l_wq) * 4,
             bbf + (size_t)(n0 + 64 + l_row) * KCAT + l_col);
        CP_COMMIT();
    }

    for (int it = 0; it < K1_NIT; it++) {
        const int buf = it & 1;
        if (it + 1 < K1_NIT) {
            const int nb = (it + 1) & 1;
            const int kk = (it + 1) * BK;
            cp16(sA + ((nb * 64 + l_row) * SSTR + l_wq) * 4,
                 abf + (size_t)(m0 + l_row) * KCAT + kk + l_col);
            cp16(sB + ((nb * 128 + l_row) * SSTR + l_wq) * 4,
                 bbf + (size_t)(n0 + l_row) * KCAT + kk + l_col);
            cp16(sB + ((nb * 128 + 64 + l_row) * SSTR + l_wq) * 4,
                 bbf + (size_t)(n0 + 64 + l_row) * KCAT + kk + l_col);
            CP_COMMIT();
            CP_WAIT1();
        } else {
            CP_WAIT0();
        }
        __syncthreads();

        const u32 aB = sA + (u32)(buf * 64 * SSTR * 4) + a_frag_off;
        const u32 bB = sB + (u32)(buf * 128 * SSTR * 4) + b_frag_off;
#pragma unroll
        for (int ks = 0; ks < 2; ks++) {
            const u32 kOff = (u32)(ks * 8 * 4);
            u32 a[2][4];
#pragma unroll
            for (int mi = 0; mi < 2; mi++)
                ldsm4(a[mi][0], a[mi][1], a[mi][2], a[mi][3],
                      aB + (u32)(mi * 16 * SSTR * 4) + kOff);
            u32 b[2][4];
#pragma unroll
            for (int nj = 0; nj < 2; nj++)
                ldsm4(b[nj][0], b[nj][1], b[nj][2], b[nj][3],
                      bB + (u32)(nj * 16 * SSTR * 4) + kOff);
#pragma unroll
            for (int mi = 0; mi < 2; mi++)
#pragma unroll
                for (int nj = 0; nj < 2; nj++) {
                    hmma16816(acc[mi][nj*2+0][0], acc[mi][nj*2+0][1],
                              acc[mi][nj*2+0][2], acc[mi][nj*2+0][3],
                              a[mi][0], a[mi][1], a[mi][2], a[mi][3],
                              b[nj][0], b[nj][1]);
                    hmma16816(acc[mi][nj*2+1][0], acc[mi][nj*2+1][1],
                              acc[mi][nj*2+1][2], acc[mi][nj*2+1][3],
                              a[mi][0], a[mi][1], a[mi][2], a[mi][3],
                              b[nj][2], b[nj][3]);
                }
        }
        __syncthreads();
    }

    // epilogue
#pragma unroll
    for (int mi = 0; mi < 2; mi++) {
        const int r0 = m0 + wm + mi * 16 + g;
#pragma unroll
        for (int ni = 0; ni < 4; ni++) {
            const int c0 = n0 + wn + ni * 8 + tig * 2;
            *(float2*)(C + (size_t)r0 * NHID + c0) =
                make_float2(acc[mi][ni][0], acc[mi][ni][1]);
            *(float2*)(C + (size_t)(r0 + 8) * NHID + c0) =
                make_float2(acc[mi][ni][2], acc[mi][ni][3]);
        }
    }
}

// ---------------------------------------------------------------------------
// K2: coalesced s/t — one warp per node, segmented reduce over 8-lane groups.
// ---------------------------------------------------------------------------
__global__ __launch_bounds__(256) void k2_st(
    const float* __restrict__ wh, const float* __restrict__ a_src,
    const float* __restrict__ a_dst,
    float* __restrict__ s, float* __restrict__ t)
{
    __shared__ float asf[NHID], adf[NHID];
    const int tid = threadIdx.x;
    if (tid < NHID) {
        asf[tid] = a_src[tid];
        adf[tid] = a_dst[tid];
    }
    __syncthreads();

    const int wid  = tid >> 5;
    const int lane = tid & 31;
    const int node = blockIdx.x * 8 + wid;
    if (node >= N_NODES) return;

    const float* row = wh + (size_t)node * NHID + lane * 8;
    float4 v0 = *(const float4*)(row + 0);
    float4 v1 = *(const float4*)(row + 4);
    const float* as = asf + lane * 8;
    const float* ad = adf + lane * 8;
    float ss = v0.x * as[0] + v0.y * as[1] + v0.z * as[2] + v0.w * as[3]
             + v1.x * as[4] + v1.y * as[5] + v1.z * as[6] + v1.w * as[7];
    float tt = v0.x * ad[0] + v0.y * ad[1] + v0.z * ad[2] + v0.w * ad[3]
             + v1.x * ad[4] + v1.y * ad[5] + v1.z * ad[6] + v1.w * ad[7];
#pragma unroll
    for (int o = 4; o; o >>= 1) {
        ss += __shfl_xor_sync(0xffffffffu, ss, o);
        tt += __shfl_xor_sync(0xffffffffu, tt, o);
    }
    if ((lane & 7) == 0) {
        int h = lane >> 3;
        s[h * N_NODES + node] = ss;
        t[h * N_NODES + node] = tt;
    }
}

// ---------------------------------------------------------------------------
// K3: fused compaction + sparse softmax + aggregation + ELU.
//     Output written directly as split-bf16 concat layout for K4.
// ---------------------------------------------------------------------------
__global__ __launch_bounds__(256) void k3_attn(
    const int* __restrict__ adj, const float* __restrict__ wh,
    const float* __restrict__ s, const float* __restrict__ t,
    __nv_bfloat16* __restrict__ h4a)
{
    __shared__ int   sidx[MAXDEG];
    __shared__ float sw[NHEADS * MAXDEG];
    __shared__ float srs[NHEADS];
    __shared__ int   scount;

    const int i   = blockIdx.x;
    const int tid = threadIdx.x;
    if (tid == 0) scount = 0;
    __syncthreads();

    const int4* arow = (const int4*)(adj + (size_t)i * N_NODES);
    for (int q = tid; q < N_NODES / 4; q += 256) {
        int4 v = arow[q];
        if (v.x) { int p = atomicAdd(&scount, 1); if (p < MAXDEG) sidx[p] = q * 4 + 0; }
        if (v.y) { int p = atomicAdd(&scount, 1); if (p < MAXDEG) sidx[p] = q * 4 + 1; }
        if (v.z) { int p = atomicAdd(&scount, 1); if (p < MAXDEG) sidx[p] = q * 4 + 2; }
        if (v.w) { int p = atomicAdd(&scount, 1); if (p < MAXDEG) sidx[p] = q * 4 + 3; }
    }
    __syncthreads();
    const int deg = min(scount, MAXDEG);

    for (int m = tid; m < deg * NHEADS; m += 256) {
        int j = m >> 2;
        int h = m & 3;
        int jj = sidx[j];
        float e = s[h * N_NODES + i] + t[h * N_NODES + jj];
        e = e > 0.f ? e : LRELU_ALPHA * e;
        sw[h * MAXDEG + j] = e;
    }
    __syncthreads();

    const int warp = tid >> 5;
    const int lane = tid & 31;
    if (warp < NHEADS) {
        const int h = warp;
        float mx = -3.4e38f;
        for (int j = lane; j < deg; j += 32) mx = fmaxf(mx, sw[h * MAXDEG + j]);
#pragma unroll
        for (int o = 16; o; o >>= 1) mx = fmaxf(mx, __shfl_xor_sync(0xffffffffu, mx, o));
        float sum = 0.f;
        for (int j = lane; j < deg; j += 32) {
            float w = __expf(sw[h * MAXDEG + j] - mx);
            sw[h * MAXDEG + j] = w;
            sum += w;
        }
#pragma unroll
        for (int o = 16; o; o >>= 1) sum += __shfl_xor_sync(0xffffffffu, sum, o);
        if (lane == 0) srs[h] = (sum > 0.f) ? 1.f / sum : 0.f;
    }
    __syncthreads();

    const int h = tid >> 6;
    float acc = 0.f;
    const float* whb = wh + tid;
#pragma unroll 4
    for (int j = 0; j < deg; j++) {
        int jj = sidx[j];
        acc += sw[h * MAXDEG + j] * whb[(size_t)jj * NHID];
    }
    acc *= srs[h];
    acc = acc > 0.f ? acc : (__expf(acc) - 1.f);

    __nv_bfloat16 hi = __float2bfloat16(acc);
    __nv_bfloat16 lo = __float2bfloat16(acc - __bfloat162float(hi));
    __nv_bfloat16* base = h4a + (size_t)i * KCAT4 + tid;
    base[0]   = hi;
    base[256] = hi;
    base[512] = lo;
}

// ---------------------------------------------------------------------------
// K4: HMMA GEMM  out = elu(h' @ lin_w'^T + b)
//     M=6144, N=128, K=768.  BM=32, BN=128 (full N), BK=32, 192 blocks.
// ---------------------------------------------------------------------------
__global__ __launch_bounds__(256) void k4_mma(
    const __nv_bfloat16* __restrict__ h4a, const __nv_bfloat16* __restrict__ b4,
    const float* __restrict__ lin_b, float* __restrict__ out)
{
    __shared__ u32 As[32][SSTR];
    __shared__ u32 Bs[128][SSTR];

    const int tid  = threadIdx.x;
    const int wid  = tid >> 5;
    const int lane = tid & 31;
    const int g    = lane >> 2;
    const int tig  = lane & 3;
    const int m0   = blockIdx.x * 32;
    const int wn   = wid * 16;

    float acc[2][2][4];
#pragma unroll
    for (int mi = 0; mi < 2; mi++)
#pragma unroll
        for (int ni = 0; ni < 2; ni++)
#pragma unroll
            for (int q = 0; q < 4; q++) acc[mi][ni][q] = 0.f;

    const int l_row = tid >> 2;
    const int l_wq  = (tid & 3) << 2;

    for (int kk = 0; kk < KCAT4; kk += BK) {
        if (tid < 128) {
            uint4 va = *(const uint4*)(h4a + (size_t)(m0 + l_row) * KCAT4 + kk + l_wq * 2);
            *(uint4*)&As[l_row][l_wq] = va;
        }
#pragma unroll
        for (int it = 0; it < 2; it++) {
            int row = l_row + it * 64;
            uint4 vb = *(const uint4*)(b4 + (size_t)row * KCAT4 + kk + l_wq * 2);
            *(uint4*)&Bs[row][l_wq] = vb;
        }
        __syncthreads();

#pragma unroll
        for (int ks = 0; ks < 2; ks++) {
            const int kw = ks * 8;
            u32 a[2][4];
#pragma unroll
            for (int mi = 0; mi < 2; mi++) {
                const int r = mi * 16;
                a[mi][0] = As[r + g    ][kw + tig];
                a[mi][1] = As[r + g + 8][kw + tig];
                a[mi][2] = As[r + g    ][kw + tig + 4];
                a[mi][3] = As[r + g + 8][kw + tig + 4];
            }
            u32 b[2][2];
#pragma unroll
            for (int ni = 0; ni < 2; ni++) {
                const int n = wn + ni * 8 + g;
                b[ni][0] = Bs[n][kw + tig];
                b[ni][1] = Bs[n][kw + tig + 4];
            }
#pragma unroll
            for (int mi = 0; mi < 2; mi++)
#pragma unroll
                for (int ni = 0; ni < 2; ni++)
                    hmma16816(acc[mi][ni][0], acc[mi][ni][1],
                              acc[mi][ni][2], acc[mi][ni][3],
                              a[mi][0], a[mi][1], a[mi][2], a[mi][3],
                              b[ni][0], b[ni][1]);
        }
        __syncthreads();
    }

#pragma unroll
    for (int mi = 0; mi < 2; mi++) {
        const int r0 = m0 + mi * 16 + g;
#pragma unroll
        for (int ni = 0; ni < 2; ni++) {
            const int c0 = wn + ni * 8 + tig * 2;
            float b0 = lin_b[c0], b1 = lin_b[c0 + 1];
            float v0 = acc[mi][ni][0] + b0;
            float v1 = acc[mi][ni][1] + b1;
            float v2 = acc[mi][ni][2] + b0;
            float v3 = acc[mi][ni][3] + b1;
            v0 = v0 > 0.f ? v0 : (__expf(v0) - 1.f);
            v1 = v1 > 0.f ? v1 : (__expf(v1) - 1.f);
            v2 = v2 > 0.f ? v2 : (__expf(v2) - 1.f);
            v3 = v3 > 0.f ? v3 : (__expf(v3) - 1.f);
            *(float2*)(out + (size_t)r0 * NEMBED + c0) = make_float2(v0, v1);
            *(float2*)(out + (size_t)(r0 + 8) * NEMBED + c0) = make_float2(v2, v3);
        }
    }
}

// ---------------------------------------------------------------------------
extern "C" void kernel_launch(void* const* d_in, const int* in_sizes, int n_in,
                              void* d_out, int out_size)
{
    const float* x     = (const float*)d_in[0];
    const int*   adj   = (const int*)  d_in[1];
    const float* W     = (const float*)d_in[2];
    const float* a_src = (const float*)d_in[3];
    const float* a_dst = (const float*)d_in[4];
    const float* lin_w = (const float*)d_in[5];
    const float* lin_b = (const float*)d_in[6];
    float* out = (float*)d_out;

    float* whcat; cudaGetSymbolAddress((void**)&whcat, g_whcat);
    float* s;     cudaGetSymbolAddress((void**)&s, g_s);
    float* t;     cudaGetSymbolAddress((void**)&t, g_t);
    __nv_bfloat16* abf; cudaGetSymbolAddress((void**)&abf, g_abf);
    __nv_bfloat16* bbf; cudaGetSymbolAddress((void**)&bbf, g_bbf);
    __nv_bfloat16* h4a; cudaGetSymbolAddress((void**)&h4a, g_h4a);
    __nv_bfloat16* b4;  cudaGetSymbolAddress((void**)&b4, g_b4);

    p1_prepA<<<(N_NODES * 128 + 255) / 256, 256>>>(x, abf);
    p2_prepB<<<(NHID * NFEAT + 255) / 256, 256>>>(W, bbf);
    p3_prepL<<<(NEMBED * NHID + 255) / 256, 256>>>(lin_w, b4);

    dim3 g1(N_NODES / 64, NHID / 128);
    k1_mma<<<g1, 256>>>(abf, bbf, whcat);

    k2_st<<<N_NODES / 8, 256>>>(whcat, a_src, a_dst, s, t);

    k3_attn<<<N_NODES, 256>>>(adj, whcat, s, t, h4a);

    k4_mma<<<N_NODES / 32, 256>>>(h4a, b4, lin_b, out);
}